// round 2
// baseline (speedup 1.0000x reference)
#include <cuda_runtime.h>
#include <math.h>

#define PI_F 3.14159265358979323846f
#define MARGIN_F 9.0f

// Problem-fixed dimensions (from reference setup_inputs)
#define DIM 512
#define HALF 256
#define NUM_REL 64

// Precomputed rotation tables: 64 relations x 256 dims of cos/sin.
// 64*256*4B*2 = 128 KB total — lives hot in L2/L1.
__device__ float g_cosT[NUM_REL * HALF];
__device__ float g_sinT[NUM_REL * HALF];

__global__ void precompute_rot_kernel(const float* __restrict__ relation_emb) {
    int i = blockIdx.x * blockDim.x + threadIdx.x;
    if (i < NUM_REL * HALF) {
        float phase = relation_emb[i] * (PI_F / MARGIN_F);
        float s, c;
        sincosf(phase, &s, &c);
        g_cosT[i] = c;
        g_sinT[i] = s;
    }
}

__device__ __forceinline__ float pair_dist(float rh, float ih, float rt, float it,
                                           float cr, float sr) {
    // re = rh*cr - ih*sr - rt ; im = rh*sr + ih*cr - it
    float re = fmaf(rh, cr, fmaf(-ih, sr, -rt));
    float im = fmaf(rh, sr, fmaf(ih, cr, -it));
    return sqrtf(fmaf(re, re, im * im));
}

// One warp per edge. Each lane handles 8 elements of the 256-wide half via
// two float4 loads at stride 32 (coalesced 512B segments).
__global__ void __launch_bounds__(256)
rotate_score_kernel(const float* __restrict__ nodes,
                    const int* __restrict__ edge_index,
                    const int* __restrict__ rel_type,
                    const float* __restrict__ temperature,
                    const float* __restrict__ bias,
                    float* __restrict__ out,
                    int num_edges) {
    int warp_id = (blockIdx.x * blockDim.x + threadIdx.x) >> 5;
    int lane = threadIdx.x & 31;
    if (warp_id >= num_edges) return;

    long long h = (long long)edge_index[warp_id];
    long long t = (long long)edge_index[num_edges + warp_id];
    int r = rel_type[warp_id];

    const float4* __restrict__ hp = (const float4*)(nodes + h * (long long)DIM);
    const float4* __restrict__ tp = (const float4*)(nodes + t * (long long)DIM);
    const float4* __restrict__ cp = (const float4*)(g_cosT + r * HALF);
    const float4* __restrict__ sp = (const float4*)(g_sinT + r * HALF);

    float acc = 0.0f;

    #pragma unroll
    for (int k = 0; k < 2; k++) {
        int j = lane + k * 32;  // float4 index within the half [0..63]

        float4 rh = hp[j];        // re_head
        float4 ih = hp[j + 64];   // im_head (second half of row)
        float4 rt = tp[j];        // re_tail
        float4 it = tp[j + 64];   // im_tail
        float4 cr = cp[j];
        float4 sr = sp[j];

        acc += pair_dist(rh.x, ih.x, rt.x, it.x, cr.x, sr.x);
        acc += pair_dist(rh.y, ih.y, rt.y, it.y, cr.y, sr.y);
        acc += pair_dist(rh.z, ih.z, rt.z, it.z, cr.z, sr.z);
        acc += pair_dist(rh.w, ih.w, rt.w, it.w, cr.w, sr.w);
    }

    // Warp-level sum reduction
    #pragma unroll
    for (int off = 16; off > 0; off >>= 1)
        acc += __shfl_down_sync(0xffffffffu, acc, off);

    if (lane == 0) {
        float mean = acc * (1.0f / (float)HALF);
        out[warp_id] = -(mean / temperature[0]) + bias[0];
    }
}

extern "C" void kernel_launch(void* const* d_in, const int* in_sizes, int n_in,
                              void* d_out, int out_size) {
    const float* nodes       = (const float*)d_in[0];
    const int*   edge_index  = (const int*)d_in[1];
    const int*   rel_type    = (const int*)d_in[2];
    const float* rel_emb     = (const float*)d_in[3];
    const float* temperature = (const float*)d_in[4];
    const float* bias        = (const float*)d_in[5];
    float*       out         = (float*)d_out;

    int num_edges = in_sizes[2];

    // Build cos/sin tables (16384 elems)
    precompute_rot_kernel<<<(NUM_REL * HALF + 255) / 256, 256>>>(rel_emb);

    // One warp per edge, 8 warps per block
    int warps_per_block = 256 / 32;
    int blocks = (num_edges + warps_per_block - 1) / warps_per_block;
    rotate_score_kernel<<<blocks, 256>>>(nodes, edge_index, rel_type,
                                         temperature, bias, out, num_edges);
}